// round 16
// baseline (speedup 1.0000x reference)
#include <cuda_runtime.h>
#include <cuda_fp16.h>
#include <cstdint>
#include <math.h>

// ---------------- problem constants ----------------
#define TOK      8192
#define HID      2048
#define FFN      7168
#define NE       8
#define NPAIR    (TOK * 2)
#define OUT_ELEMS ((size_t)TOK * HID)
#define MT       256            // GEMM m-tile rows
#define MAXT     72             // 16384/256 + NE
#define NCHUNK1  (FFN / 64)     // 112 gemm1 n-chunks per m-tile
#define NCHUNK2  (HID / 128)    // 16 gemm2 n-chunks per m-tile

// ---------------- device scratch ----------------
__device__ int      g_cnt[NE];
__device__ int      g_off[NE];
__device__ int      g_cur[NE];
__device__ int      g_ntiles;
__device__ int      g_tile_e[MAXT];
__device__ int      g_tile_m[MAXT];
__device__ int      g_sel[NPAIR];
__device__ float    g_selw[NPAIR];
__device__ int      g_ptok[NPAIR];
__device__ float    g_pw[NPAIR];
__device__ int      g_pe[NPAIR];
__device__ float    g_logit_dump[TOK * NE];
__device__ __half   g_xg[(size_t)NPAIR * HID];    // scaled activations, fp16
__device__ __half   g_hmid[(size_t)NPAIR * FFN];  // silu(xw1)*(xw3)*wr, fp16
__device__ unsigned g_qhead;                      // work-queue head
__device__ unsigned g_done1[MAXT];                // per-m-tile gemm1 completion count
__device__ int      g_n1, g_ntotal;               // queue sizes

// ---------------- helpers ----------------
__device__ __forceinline__ void mma_f16(float c[4], const unsigned a[4], const unsigned b[2]) {
    asm volatile(
        "mma.sync.aligned.m16n8k16.row.col.f32.f16.f16.f32 "
        "{%0,%1,%2,%3}, {%4,%5,%6,%7}, {%8,%9}, {%0,%1,%2,%3};\n"
        : "+f"(c[0]), "+f"(c[1]), "+f"(c[2]), "+f"(c[3])
        : "r"(a[0]), "r"(a[1]), "r"(a[2]), "r"(a[3]), "r"(b[0]), "r"(b[1]));
}

#define LDSM_X4(r0, r1, r2, r3, addr) \
    asm volatile("ldmatrix.sync.aligned.m8n8.x4.shared.b16 {%0,%1,%2,%3}, [%4];" \
                 : "=r"(r0), "=r"(r1), "=r"(r2), "=r"(r3) : "r"(addr))

__device__ __forceinline__ void cp_async16(uint32_t saddr, const void* gptr, int szbytes) {
    asm volatile("cp.async.cg.shared.global [%0], [%1], 16, %2;\n"
                 :: "r"(saddr), "l"(gptr), "r"(szbytes));
}
#define CP_COMMIT() asm volatile("cp.async.commit_group;\n" ::)
#define CP_WAIT(n)  asm volatile("cp.async.wait_group %0;\n" :: "n"(n))

#define STS128U(addr, a, b, c, d) \
    asm volatile("st.shared.v4.b32 [%0], {%1, %2, %3, %4};" \
                 :: "r"(addr), "r"(a), "r"(b), "r"(c), "r"(d) : "memory")

__device__ __forceinline__ uint32_t pack_h2(float lo, float hi) {
    __half2 h = __floats2half2_rn(lo, hi);
    return *reinterpret_cast<uint32_t*>(&h);
}

// ---------------- kernel 0: zero output + counters ----------------
__global__ void init_kernel(float4* out4) {
    size_t i      = (size_t)blockIdx.x * blockDim.x + threadIdx.x;
    size_t stride = (size_t)gridDim.x * blockDim.x;
    const size_t n4 = OUT_ELEMS / 4;
    float4 z = make_float4(0.f, 0.f, 0.f, 0.f);
    for (size_t j = i; j < n4; j += stride) out4[j] = z;
    if (blockIdx.x == 0 && threadIdx.x < NE) g_cnt[threadIdx.x] = 0;
}

// ---------------- kernel 1: router ----------------
__global__ void router_kernel(const float* __restrict__ x,
                              const float* __restrict__ gate,
                              float* __restrict__ logits_out,
                              int write_logits) {
    int warp = threadIdx.x >> 5;
    int lane = threadIdx.x & 31;
    int tbase = blockIdx.x * 64 + warp * 8;

    for (int i = 0; i < 8; i++) {
        int t = tbase + i;
        const float4* xp = (const float4*)(x + (size_t)t * HID);
        float acc[NE];
#pragma unroll
        for (int e = 0; e < NE; e++) acc[e] = 0.f;
        for (int c = lane; c < HID / 4; c += 32) {
            float4 xv = __ldg(xp + c);
#pragma unroll
            for (int e = 0; e < NE; e++) {
                float4 gv = __ldg((const float4*)(gate + (size_t)e * HID) + c);
                acc[e] += xv.x * gv.x + xv.y * gv.y + xv.z * gv.z + xv.w * gv.w;
            }
        }
#pragma unroll
        for (int e = 0; e < NE; e++)
            for (int o = 16; o; o >>= 1) acc[e] += __shfl_xor_sync(0xffffffffu, acc[e], o);

        if (lane == 0) {
            float* lo = write_logits ? logits_out : g_logit_dump;
#pragma unroll
            for (int e = 0; e < NE; e++) lo[(size_t)t * NE + e] = acc[e];
            int e0 = 0;
            for (int e = 1; e < NE; e++) if (acc[e] > acc[e0]) e0 = e;
            int e1 = -1;
            for (int e = 0; e < NE; e++) {
                if (e == e0) continue;
                if (e1 < 0 || acc[e] > acc[e1]) e1 = e;
            }
            float w0 = 1.f / (1.f + expf(acc[e1] - acc[e0]));
            float w1 = 1.f - w0;
            g_sel[t * 2 + 0] = e0; g_selw[t * 2 + 0] = w0;
            g_sel[t * 2 + 1] = e1; g_selw[t * 2 + 1] = w1;
            atomicAdd(&g_cnt[e0], 1);
            atomicAdd(&g_cnt[e1], 1);
        }
    }
}

// ---------------- kernel 2: scan + tile list + queue reset ----------------
__global__ void scan_kernel() {
    if (threadIdx.x == 0) {
        int o = 0, nt = 0;
        for (int e = 0; e < NE; e++) {
            g_off[e] = o;
            g_cur[e] = o;
            int c = g_cnt[e];
            int tl = (c + MT - 1) / MT;
            for (int m = 0; m < tl; m++) { g_tile_e[nt] = e; g_tile_m[nt] = m; nt++; }
            o += c;
        }
        g_ntiles = nt;
        g_n1     = nt * NCHUNK1;
        g_ntotal = nt * NCHUNK1 + nt * NCHUNK2;
        g_qhead  = 0;
    }
    for (int i = threadIdx.x; i < MAXT; i += blockDim.x) g_done1[i] = 0;
}

// ---------------- kernel 3: scatter ----------------
__global__ void scatter_kernel() {
    int t = blockIdx.x * blockDim.x + threadIdx.x;
    if (t >= TOK) return;
#pragma unroll
    for (int k = 0; k < 2; k++) {
        int e = g_sel[t * 2 + k];
        int pos = atomicAdd(&g_cur[e], 1);
        g_ptok[pos] = t;
        g_pw[pos]   = g_selw[t * 2 + k];
        g_pe[pos]   = e;
    }
}

// ---------------- kernel 4: gather + scale divide -> fp16 ----------------
__global__ void gather_kernel(const float* __restrict__ x,
                              const float* __restrict__ scales) {
    int r = blockIdx.x;
    int tok = g_ptok[r];
    int e   = g_pe[r];
    const float4* xp = (const float4*)(x + (size_t)tok * HID);
    const float4* sp = (const float4*)(scales + (size_t)e * HID);
    uint32_t* dp = (uint32_t*)(g_xg + (size_t)r * HID);
    for (int c = threadIdx.x; c < HID / 4; c += blockDim.x) {
        float4 xv = xp[c], sv = sp[c];
        dp[c * 2 + 0] = pack_h2(xv.x / sv.x, xv.y / sv.y);
        dp[c * 2 + 1] = pack_h2(xv.z / sv.z, xv.w / sv.w);
    }
}

// ================== GEMM config (fp16 operands, fp32 accum) ==================
#define BKH     64                        // k per mainloop iter (halfs)
#define PADH    72                        // halfs per smem row (144B, conflict-free)
#define STAGES  4
#define A_STH   (MT * PADH)               // 18432 halfs per A stage
#define A_TOTH  (STAGES * A_STH)          // 73728 halfs
#define B_ROWS  128
#define B_STH   (B_ROWS * PADH)           // 9216 halfs per B buffer
#define SMEM_DYN ((A_TOTH + 2 * B_STH) * 2)   // 184320 B

// ---------------- gemm1 tile: hmid[ti, n-chunk] = silu(xg@w1^T)*(xg@w3^T)*wr ----------------
__device__ void gemm1_tile(int ti, int nx,
                           const float* __restrict__ w1,
                           const float* __restrict__ w3) {
    int e    = g_tile_e[ti];
    int mt   = g_tile_m[ti];
    int cnt  = g_cnt[e];
    int off  = g_off[e];
    int row0 = off + mt * MT;
    int mrows = cnt - mt * MT; if (mrows > MT) mrows = MT;
    int n0 = nx * 64;

    extern __shared__ __half sm[];
    uint32_t smb = (uint32_t)__cvta_generic_to_shared(sm);

    int tid  = threadIdx.x;
    int wid  = tid >> 5, lane = tid & 31;
    int wm   = (wid & 3) * 64;
    int wn   = (wid >> 2) * 16;
    int lr   = lane >> 2, lc = lane & 3;

    uint32_t lm_off = (uint32_t)(((lane & 15) * PADH + (lane >> 4) * 8) * 2);

    const float* w1p = w1 + ((size_t)e * FFN + n0) * HID;
    const float* w3p = w3 + ((size_t)e * FFN + n0) * HID;

    // B producers: 128 rows x 8 chunks (8 halfs) = 1024 chunks; 2 per thread
    const float* bsrc[2];
    uint32_t     bdst[2];
#pragma unroll
    for (int q = 0; q < 2; q++) {
        int idx = tid + q * 512;
        int row = idx >> 3, c8 = idx & 7;
        bsrc[q] = ((row < 64) ? (w1p + (size_t)row * HID)
                              : (w3p + (size_t)(row - 64) * HID)) + c8 * 8;
        bdst[q] = smb + (uint32_t)((A_TOTH + row * PADH + c8 * 8) * 2);
    }

    float c1[4][2][4], c2[4][2][4];
#pragma unroll
    for (int i = 0; i < 4; i++)
#pragma unroll
        for (int j = 0; j < 2; j++)
#pragma unroll
            for (int q = 0; q < 4; q++) { c1[i][j][q] = 0.f; c2[i][j][q] = 0.f; }

    auto loadA = [&](int st, int k0) {
        uint32_t sb = smb + (uint32_t)(st * A_STH * 2);
#pragma unroll
        for (int j = 0; j < 4; j++) {
            int idx = j * 512 + tid;
            int row = idx >> 3, c8 = idx & 7;
            int p = (row < mrows) ? 16 : 0;
            cp_async16(sb + (uint32_t)((row * PADH + c8 * 8) * 2),
                       g_xg + (size_t)(row0 + row) * HID + k0 + c8 * 8, p);
        }
    };

    float4 rb[2][2];
    auto ldgB = [&](int k0) {
#pragma unroll
        for (int q = 0; q < 2; q++) {
            rb[q][0] = *(const float4*)(bsrc[q] + k0);
            rb[q][1] = *(const float4*)(bsrc[q] + k0 + 4);
        }
    };
    auto stsB = [&](int buf) {
#pragma unroll
        for (int q = 0; q < 2; q++) {
            STS128U(bdst[q] + (uint32_t)(buf * B_STH * 2),
                    pack_h2(rb[q][0].x, rb[q][0].y), pack_h2(rb[q][0].z, rb[q][0].w),
                    pack_h2(rb[q][1].x, rb[q][1].y), pack_h2(rb[q][1].z, rb[q][1].w));
        }
    };

    const int nk = HID / BKH;   // 32

    ldgB(0);
    loadA(0, 0);       CP_COMMIT();
    loadA(1, BKH);     CP_COMMIT();
    loadA(2, 2 * BKH); CP_COMMIT();
    stsB(0);
    ldgB(BKH);

    for (int i = 0; i < nk; i++) {
        CP_WAIT(2);
        __syncthreads();
        uint32_t Sb = smb + (uint32_t)((i & 3) * A_STH * 2);
        uint32_t Bb = smb + (uint32_t)((A_TOTH + (i & 1) * B_STH) * 2);
#pragma unroll
        for (int ko = 0; ko < BKH; ko += 16) {
            unsigned a[4][4], b1[2][2], b3[2][2];
#pragma unroll
            for (int s = 0; s < 4; s++) {
                uint32_t ad = Sb + (uint32_t)(((wm + s * 16) * PADH + ko) * 2) + lm_off;
                LDSM_X4(a[s][0], a[s][1], a[s][2], a[s][3], ad);
            }
            {
                uint32_t bd1 = Bb + (uint32_t)((wn * PADH + ko) * 2) + lm_off;
                unsigned r0, r1, r2, r3;
                LDSM_X4(r0, r1, r2, r3, bd1);
                b1[0][0] = r0; b1[1][0] = r1; b1[0][1] = r2; b1[1][1] = r3;
                uint32_t bd3 = Bb + (uint32_t)(((64 + wn) * PADH + ko) * 2) + lm_off;
                LDSM_X4(r0, r1, r2, r3, bd3);
                b3[0][0] = r0; b3[1][0] = r1; b3[0][1] = r2; b3[1][1] = r3;
            }
#pragma unroll
            for (int s = 0; s < 4; s++)
#pragma unroll
                for (int sn = 0; sn < 2; sn++) {
                    mma_f16(c1[s][sn], a[s], b1[sn]);
                    mma_f16(c2[s][sn], a[s], b3[sn]);
                }
        }
        if (i + 1 < nk) {
            stsB((i + 1) & 1);
            if (i + 2 < nk) ldgB((i + 2) * BKH);
        }
        if (i + 3 < nk) loadA((i + 3) & 3, (i + 3) * BKH);
        CP_COMMIT();
    }
    CP_WAIT(0);

    // epilogue: hmid = silu(c1) * c2 * wr -> fp16
#pragma unroll
    for (int s = 0; s < 4; s++) {
#pragma unroll
        for (int half = 0; half < 2; half++) {
            int r = wm + s * 16 + half * 8 + lr;
            if (r < mrows) {
                float wr = g_pw[row0 + r];
                __half* hp = g_hmid + (size_t)(row0 + r) * FFN + n0;
#pragma unroll
                for (int sn = 0; sn < 2; sn++) {
                    int col = wn + sn * 8 + lc * 2;
                    float v1a = c1[s][sn][half * 2 + 0], v3a = c2[s][sn][half * 2 + 0];
                    float v1b = c1[s][sn][half * 2 + 1], v3b = c2[s][sn][half * 2 + 1];
                    float oa = (v1a / (1.f + expf(-v1a))) * v3a * wr;
                    float ob = (v1b / (1.f + expf(-v1b))) * v3b * wr;
                    *(uint32_t*)(hp + col) = pack_h2(oa, ob);
                }
            }
        }
    }

    // publish: hmid stores visible, then bump completion counter
    __threadfence();
    __syncthreads();
    if (tid == 0) atomicAdd(&g_done1[ti], 1u);
}

// ---------------- gemm2 tile: out[tok, n-chunk] += hmid @ w2^T ----------------
__device__ void gemm2_tile(int ti, int nx,
                           const float* __restrict__ w2,
                           float* __restrict__ out) {
    int e    = g_tile_e[ti];
    int mt   = g_tile_m[ti];
    int cnt  = g_cnt[e];
    int off  = g_off[e];
    int row0 = off + mt * MT;
    int mrows = cnt - mt * MT; if (mrows > MT) mrows = MT;
    int n0 = nx * 128;

    // wait for all gemm1 chunks of this m-tile
    if (threadIdx.x == 0) {
        while (atomicAdd(&g_done1[ti], 0u) < (unsigned)NCHUNK1) __nanosleep(200);
    }
    __syncthreads();
    __threadfence();

    extern __shared__ __half sm[];
    uint32_t smb = (uint32_t)__cvta_generic_to_shared(sm);

    int tid  = threadIdx.x;
    int wid  = tid >> 5, lane = tid & 31;
    int wm   = (wid & 3) * 64;
    int wn   = (wid >> 2) * 32;
    int lr   = lane >> 2, lc = lane & 3;

    uint32_t lm_off = (uint32_t)(((lane & 15) * PADH + (lane >> 4) * 8) * 2);

    const float* w2p = w2 + ((size_t)e * HID + n0) * FFN;

    const float* bsrc[2];
    uint32_t     bdst[2];
#pragma unroll
    for (int q = 0; q < 2; q++) {
        int idx = tid + q * 512;
        int row = idx >> 3, c8 = idx & 7;
        bsrc[q] = w2p + (size_t)row * FFN + c8 * 8;
        bdst[q] = smb + (uint32_t)((A_TOTH + row * PADH + c8 * 8) * 2);
    }

    float cc[4][4][4];
#pragma unroll
    for (int i = 0; i < 4; i++)
#pragma unroll
        for (int j = 0; j < 4; j++)
#pragma unroll
            for (int q = 0; q < 4; q++) cc[i][j][q] = 0.f;

    auto loadA = [&](int st, int k0) {
        uint32_t sb = smb + (uint32_t)(st * A_STH * 2);
#pragma unroll
        for (int j = 0; j < 4; j++) {
            int idx = j * 512 + tid;
            int row = idx >> 3, c8 = idx & 7;
            int p = (row < mrows) ? 16 : 0;
            cp_async16(sb + (uint32_t)((row * PADH + c8 * 8) * 2),
                       g_hmid + (size_t)(row0 + row) * FFN + k0 + c8 * 8, p);
        }
    };

    float4 rb[2][2];
    auto ldgB = [&](int k0) {
#pragma unroll
        for (int q = 0; q < 2; q++) {
            rb[q][0] = *(const float4*)(bsrc[q] + k0);
            rb[q][1] = *(const float4*)(bsrc[q] + k0 + 4);
        }
    };
    auto stsB = [&](int buf) {
#pragma unroll
        for (int q = 0; q < 2; q++) {
            STS128U(bdst[q] + (uint32_t)(buf * B_STH * 2),
                    pack_h2(rb[q][0].x, rb[q][0].y), pack_h2(rb[q][0].z, rb[q][0].w),
                    pack_h2(rb[q][1].x, rb[q][1].y), pack_h2(rb[q][1].z, rb[q][1].w));
        }
    };

    const int nk = FFN / BKH;   // 112

    ldgB(0);
    loadA(0, 0);       CP_COMMIT();
    loadA(1, BKH);     CP_COMMIT();
    loadA(2, 2 * BKH); CP_COMMIT();
    stsB(0);
    ldgB(BKH);

    for (int i = 0; i < nk; i++) {
        CP_WAIT(2);
        __syncthreads();
        uint32_t Sb = smb + (uint32_t)((i & 3) * A_STH * 2);
        uint32_t Bb = smb + (uint32_t)((A_TOTH + (i & 1) * B_STH) * 2);
#pragma unroll
        for (int ko = 0; ko < BKH; ko += 16) {
            unsigned a[4][4], b[4][2];
#pragma unroll
            for (int s = 0; s < 4; s++) {
                uint32_t ad = Sb + (uint32_t)(((wm + s * 16) * PADH + ko) * 2) + lm_off;
                LDSM_X4(a[s][0], a[s][1], a[s][2], a[s][3], ad);
            }
            {
                unsigned r0, r1, r2, r3;
                uint32_t bd0 = Bb + (uint32_t)((wn * PADH + ko) * 2) + lm_off;
                LDSM_X4(r0, r1, r2, r3, bd0);
                b[0][0] = r0; b[1][0] = r1; b[0][1] = r2; b[1][1] = r3;
                uint32_t bd1 = Bb + (uint32_t)(((wn + 16) * PADH + ko) * 2) + lm_off;
                LDSM_X4(r0, r1, r2, r3, bd1);
                b[2][0] = r0; b[3][0] = r1; b[2][1] = r2; b[3][1] = r3;
            }
#pragma unroll
            for (int s = 0; s < 4; s++)
#pragma unroll
                for (int sn = 0; sn < 4; sn++)
                    mma_f16(cc[s][sn], a[s], b[sn]);
        }
        if (i + 1 < nk) {
            stsB((i + 1) & 1);
            if (i + 2 < nk) ldgB((i + 2) * BKH);
        }
        if (i + 3 < nk) loadA((i + 3) & 3, (i + 3) * BKH);
        CP_COMMIT();
    }
    CP_WAIT(0);

    // epilogue: atomic scatter-add into out[token][h]
#pragma unroll
    for (int s = 0; s < 4; s++) {
#pragma unroll
        for (int half = 0; half < 2; half++) {
            int r = wm + s * 16 + half * 8 + lr;
            if (r < mrows) {
                int tok = g_ptok[row0 + r];
                float* op = out + (size_t)tok * HID + n0;
#pragma unroll
                for (int sn = 0; sn < 4; sn++) {
                    int col = wn + sn * 8 + lc * 2;
                    atomicAdd(&op[col + 0], cc[s][sn][half * 2 + 0]);
                    atomicAdd(&op[col + 1], cc[s][sn][half * 2 + 1]);
                }
            }
        }
    }
}

// ---------------- fused persistent GEMM kernel ----------------
__global__ __launch_bounds__(512, 1) void mm_kernel(const float* __restrict__ w1,
                                                    const float* __restrict__ w3,
                                                    const float* __restrict__ w2,
                                                    float* __restrict__ out) {
    __shared__ int s_item;
    const int n1   = g_n1;
    const int ntot = g_ntotal;

    while (true) {
        __syncthreads();   // all warps done with previous item's smem
        if (threadIdx.x == 0) s_item = (int)atomicAdd(&g_qhead, 1u);
        __syncthreads();
        int id = s_item;
        if (id >= ntot) break;
        if (id < n1) {
            gemm1_tile(id / NCHUNK1, id % NCHUNK1, w1, w3);
        } else {
            int id2 = id - n1;
            gemm2_tile(id2 / NCHUNK2, id2 % NCHUNK2, w2, out);
        }
    }
}

// ---------------- host launch ----------------
extern "C" void kernel_launch(void* const* d_in, const int* in_sizes, int n_in,
                              void* d_out, int out_size) {
    const float* x      = (const float*)d_in[0];
    const float* gate   = (const float*)d_in[1];
    const float* w1     = (const float*)d_in[2];
    const float* w3     = (const float*)d_in[3];
    const float* w2     = (const float*)d_in[4];
    const float* scales = (const float*)d_in[5];

    float* out = (float*)d_out;
    int write_logits = ((size_t)out_size >= OUT_ELEMS + (size_t)TOK * NE) ? 1 : 0;
    float* logits = out + OUT_ELEMS;

    cudaFuncSetAttribute(mm_kernel, cudaFuncAttributeMaxDynamicSharedMemorySize, SMEM_DYN);

    init_kernel<<<2048, 256>>>((float4*)out);
    router_kernel<<<TOK / 64, 256>>>(x, gate, logits, write_logits);
    scan_kernel<<<1, 128>>>();
    scatter_kernel<<<TOK / 256, 256>>>();
    gather_kernel<<<NPAIR, 128>>>(x, scales);

    mm_kernel<<<152, 512, SMEM_DYN>>>(w1, w3, w2, out);
}

// round 17
// speedup vs baseline: 1.0174x; 1.0174x over previous
#include <cuda_runtime.h>
#include <cuda_fp16.h>
#include <cstdint>
#include <math.h>

// ---------------- problem constants ----------------
#define TOK      8192
#define HID      2048
#define FFN      7168
#define NE       8
#define NPAIR    (TOK * 2)
#define OUT_ELEMS ((size_t)TOK * HID)
#define MT       256            // GEMM m-tile rows
#define MAXT     72             // 16384/256 + NE
#define NCHUNK1  (FFN / 64)     // 112 gemm1 n-chunks per m-tile
#define NCHUNK2  (HID / 128)    // 16 gemm2 n-chunks per m-tile

// ---------------- device scratch ----------------
__device__ int      g_cnt[NE];
__device__ int      g_off[NE];
__device__ int      g_cur[NE];
__device__ int      g_ntiles;
__device__ int      g_tile_e[MAXT];
__device__ int      g_tile_m[MAXT];
__device__ int      g_sel[NPAIR];
__device__ float    g_selw[NPAIR];
__device__ int      g_ptok[NPAIR];
__device__ float    g_pw[NPAIR];
__device__ int      g_pe[NPAIR];
__device__ float    g_logit_dump[TOK * NE];
__device__ __half   g_xg[(size_t)NPAIR * HID];    // scaled activations, fp16
__device__ __half   g_hmid[(size_t)NPAIR * FFN];  // silu(xw1)*(xw3)*wr, fp16
__device__ unsigned g_qhead;                      // work-queue head
__device__ unsigned g_done1[MAXT];                // per-m-tile gemm1 completion count
__device__ int      g_n1, g_ntotal;               // queue sizes

// ---------------- helpers ----------------
__device__ __forceinline__ void mma_f16(float c[4], const unsigned a[4], const unsigned b[2]) {
    asm volatile(
        "mma.sync.aligned.m16n8k16.row.col.f32.f16.f16.f32 "
        "{%0,%1,%2,%3}, {%4,%5,%6,%7}, {%8,%9}, {%0,%1,%2,%3};\n"
        : "+f"(c[0]), "+f"(c[1]), "+f"(c[2]), "+f"(c[3])
        : "r"(a[0]), "r"(a[1]), "r"(a[2]), "r"(a[3]), "r"(b[0]), "r"(b[1]));
}

#define LDSM_X4(r0, r1, r2, r3, addr) \
    asm volatile("ldmatrix.sync.aligned.m8n8.x4.shared.b16 {%0,%1,%2,%3}, [%4];" \
                 : "=r"(r0), "=r"(r1), "=r"(r2), "=r"(r3) : "r"(addr))

__device__ __forceinline__ void cp_async16(uint32_t saddr, const void* gptr, int szbytes) {
    asm volatile("cp.async.cg.shared.global [%0], [%1], 16, %2;\n"
                 :: "r"(saddr), "l"(gptr), "r"(szbytes));
}
#define CP_COMMIT() asm volatile("cp.async.commit_group;\n" ::)
#define CP_WAIT(n)  asm volatile("cp.async.wait_group %0;\n" :: "n"(n))

#define STS128U(addr, a, b, c, d) \
    asm volatile("st.shared.v4.b32 [%0], {%1, %2, %3, %4};" \
                 :: "r"(addr), "r"(a), "r"(b), "r"(c), "r"(d) : "memory")

__device__ __forceinline__ uint32_t pack_h2(float lo, float hi) {
    __half2 h = __floats2half2_rn(lo, hi);
    return *reinterpret_cast<uint32_t*>(&h);
}

// ---------------- kernel 0: zero output + counters ----------------
__global__ void init_kernel(float4* out4) {
    size_t i      = (size_t)blockIdx.x * blockDim.x + threadIdx.x;
    size_t stride = (size_t)gridDim.x * blockDim.x;
    const size_t n4 = OUT_ELEMS / 4;
    float4 z = make_float4(0.f, 0.f, 0.f, 0.f);
    for (size_t j = i; j < n4; j += stride) out4[j] = z;
    if (blockIdx.x == 0 && threadIdx.x < NE) g_cnt[threadIdx.x] = 0;
}

// ---------------- kernel 1: router ----------------
__global__ void router_kernel(const float* __restrict__ x,
                              const float* __restrict__ gate,
                              float* __restrict__ logits_out,
                              int write_logits) {
    int warp = threadIdx.x >> 5;
    int lane = threadIdx.x & 31;
    int tbase = blockIdx.x * 64 + warp * 8;

    for (int i = 0; i < 8; i++) {
        int t = tbase + i;
        const float4* xp = (const float4*)(x + (size_t)t * HID);
        float acc[NE];
#pragma unroll
        for (int e = 0; e < NE; e++) acc[e] = 0.f;
        for (int c = lane; c < HID / 4; c += 32) {
            float4 xv = __ldg(xp + c);
#pragma unroll
            for (int e = 0; e < NE; e++) {
                float4 gv = __ldg((const float4*)(gate + (size_t)e * HID) + c);
                acc[e] += xv.x * gv.x + xv.y * gv.y + xv.z * gv.z + xv.w * gv.w;
            }
        }
#pragma unroll
        for (int e = 0; e < NE; e++)
            for (int o = 16; o; o >>= 1) acc[e] += __shfl_xor_sync(0xffffffffu, acc[e], o);

        if (lane == 0) {
            float* lo = write_logits ? logits_out : g_logit_dump;
#pragma unroll
            for (int e = 0; e < NE; e++) lo[(size_t)t * NE + e] = acc[e];
            int e0 = 0;
            for (int e = 1; e < NE; e++) if (acc[e] > acc[e0]) e0 = e;
            int e1 = -1;
            for (int e = 0; e < NE; e++) {
                if (e == e0) continue;
                if (e1 < 0 || acc[e] > acc[e1]) e1 = e;
            }
            float w0 = 1.f / (1.f + expf(acc[e1] - acc[e0]));
            float w1 = 1.f - w0;
            g_sel[t * 2 + 0] = e0; g_selw[t * 2 + 0] = w0;
            g_sel[t * 2 + 1] = e1; g_selw[t * 2 + 1] = w1;
            atomicAdd(&g_cnt[e0], 1);
            atomicAdd(&g_cnt[e1], 1);
        }
    }
}

// ---------------- kernel 2: scan + tile list + queue reset ----------------
__global__ void scan_kernel() {
    if (threadIdx.x == 0) {
        int o = 0, nt = 0;
        for (int e = 0; e < NE; e++) {
            g_off[e] = o;
            g_cur[e] = o;
            int c = g_cnt[e];
            int tl = (c + MT - 1) / MT;
            for (int m = 0; m < tl; m++) { g_tile_e[nt] = e; g_tile_m[nt] = m; nt++; }
            o += c;
        }
        g_ntiles = nt;
        g_n1     = nt * NCHUNK1;
        g_ntotal = nt * NCHUNK1 + nt * NCHUNK2;
        g_qhead  = 0;
    }
    for (int i = threadIdx.x; i < MAXT; i += blockDim.x) g_done1[i] = 0;
}

// ---------------- kernel 3: scatter ----------------
__global__ void scatter_kernel() {
    int t = blockIdx.x * blockDim.x + threadIdx.x;
    if (t >= TOK) return;
#pragma unroll
    for (int k = 0; k < 2; k++) {
        int e = g_sel[t * 2 + k];
        int pos = atomicAdd(&g_cur[e], 1);
        g_ptok[pos] = t;
        g_pw[pos]   = g_selw[t * 2 + k];
        g_pe[pos]   = e;
    }
}

// ---------------- kernel 4: gather + scale divide -> fp16 ----------------
__global__ void gather_kernel(const float* __restrict__ x,
                              const float* __restrict__ scales) {
    int r = blockIdx.x;
    int tok = g_ptok[r];
    int e   = g_pe[r];
    const float4* xp = (const float4*)(x + (size_t)tok * HID);
    const float4* sp = (const float4*)(scales + (size_t)e * HID);
    uint32_t* dp = (uint32_t*)(g_xg + (size_t)r * HID);
    for (int c = threadIdx.x; c < HID / 4; c += blockDim.x) {
        float4 xv = xp[c], sv = sp[c];
        dp[c * 2 + 0] = pack_h2(xv.x / sv.x, xv.y / sv.y);
        dp[c * 2 + 1] = pack_h2(xv.z / sv.z, xv.w / sv.w);
    }
}

// ================== GEMM config (fp16 operands, fp32 accum) ==================
#define BKH     64                        // k per mainloop iter (halfs)
#define PADH    72                        // halfs per smem row (144B, conflict-free)
#define STAGES  3
#define A_STH   (MT * PADH)               // 18432 halfs per A stage
#define A_TOTH  (STAGES * A_STH)          // 55296 halfs
#define B_ROWS  128
#define B_STH   (B_ROWS * PADH)           // 9216 halfs per B buffer
#define SMEM_DYN ((A_TOTH + 2 * B_STH) * 2)   // 147456 B

// ---------------- gemm1 tile: hmid[ti, n-chunk] = silu(xg@w1^T)*(xg@w3^T)*wr ----------------
__device__ void gemm1_tile(int ti, int nx,
                           const float* __restrict__ w1,
                           const float* __restrict__ w3) {
    int e    = g_tile_e[ti];
    int mt   = g_tile_m[ti];
    int cnt  = g_cnt[e];
    int off  = g_off[e];
    int row0 = off + mt * MT;
    int mrows = cnt - mt * MT; if (mrows > MT) mrows = MT;
    int n0 = nx * 64;

    extern __shared__ __half sm[];
    uint32_t smb = (uint32_t)__cvta_generic_to_shared(sm);

    int tid  = threadIdx.x;
    int wid  = tid >> 5, lane = tid & 31;
    int wm   = (wid & 3) * 64;
    int wn   = (wid >> 2) * 16;
    int lr   = lane >> 2, lc = lane & 3;

    uint32_t lm_off = (uint32_t)(((lane & 15) * PADH + (lane >> 4) * 8) * 2);

    const float* w1p = w1 + ((size_t)e * FFN + n0) * HID;
    const float* w3p = w3 + ((size_t)e * FFN + n0) * HID;

    // B producers: 128 rows x 8 chunks (8 halfs) = 1024 chunks; 2 per thread
    const float* bsrc[2];
    uint32_t     bdst[2];
#pragma unroll
    for (int q = 0; q < 2; q++) {
        int idx = tid + q * 512;
        int row = idx >> 3, c8 = idx & 7;
        bsrc[q] = ((row < 64) ? (w1p + (size_t)row * HID)
                              : (w3p + (size_t)(row - 64) * HID)) + c8 * 8;
        bdst[q] = smb + (uint32_t)((A_TOTH + row * PADH + c8 * 8) * 2);
    }

    float c1[4][2][4], c2[4][2][4];
#pragma unroll
    for (int i = 0; i < 4; i++)
#pragma unroll
        for (int j = 0; j < 2; j++)
#pragma unroll
            for (int q = 0; q < 4; q++) { c1[i][j][q] = 0.f; c2[i][j][q] = 0.f; }

    auto loadA = [&](int st, int k0) {
        uint32_t sb = smb + (uint32_t)(st * A_STH * 2);
#pragma unroll
        for (int j = 0; j < 4; j++) {
            int idx = j * 512 + tid;
            int row = idx >> 3, c8 = idx & 7;
            int p = (row < mrows) ? 16 : 0;
            cp_async16(sb + (uint32_t)((row * PADH + c8 * 8) * 2),
                       g_xg + (size_t)(row0 + row) * HID + k0 + c8 * 8, p);
        }
    };

    float4 rb[2][2];
    auto ldgB = [&](int k0) {
#pragma unroll
        for (int q = 0; q < 2; q++) {
            rb[q][0] = *(const float4*)(bsrc[q] + k0);
            rb[q][1] = *(const float4*)(bsrc[q] + k0 + 4);
        }
    };
    auto stsB = [&](int buf) {
#pragma unroll
        for (int q = 0; q < 2; q++) {
            STS128U(bdst[q] + (uint32_t)(buf * B_STH * 2),
                    pack_h2(rb[q][0].x, rb[q][0].y), pack_h2(rb[q][0].z, rb[q][0].w),
                    pack_h2(rb[q][1].x, rb[q][1].y), pack_h2(rb[q][1].z, rb[q][1].w));
        }
    };

    const int nk = HID / BKH;   // 32

    ldgB(0);
    loadA(0, 0);   CP_COMMIT();
    loadA(1, BKH); CP_COMMIT();
    stsB(0);
    ldgB(BKH);

    for (int i = 0; i < nk; i++) {
        CP_WAIT(1);
        __syncthreads();
        uint32_t Sb = smb + (uint32_t)((i % 3) * A_STH * 2);
        uint32_t Bb = smb + (uint32_t)((A_TOTH + (i & 1) * B_STH) * 2);
#pragma unroll
        for (int ko = 0; ko < BKH; ko += 16) {
            unsigned a[4][4], b1[2][2], b3[2][2];
#pragma unroll
            for (int s = 0; s < 4; s++) {
                uint32_t ad = Sb + (uint32_t)(((wm + s * 16) * PADH + ko) * 2) + lm_off;
                LDSM_X4(a[s][0], a[s][1], a[s][2], a[s][3], ad);
            }
            {
                uint32_t bd1 = Bb + (uint32_t)((wn * PADH + ko) * 2) + lm_off;
                unsigned r0, r1, r2, r3;
                LDSM_X4(r0, r1, r2, r3, bd1);
                b1[0][0] = r0; b1[1][0] = r1; b1[0][1] = r2; b1[1][1] = r3;
                uint32_t bd3 = Bb + (uint32_t)(((64 + wn) * PADH + ko) * 2) + lm_off;
                LDSM_X4(r0, r1, r2, r3, bd3);
                b3[0][0] = r0; b3[1][0] = r1; b3[0][1] = r2; b3[1][1] = r3;
            }
#pragma unroll
            for (int s = 0; s < 4; s++)
#pragma unroll
                for (int sn = 0; sn < 2; sn++) {
                    mma_f16(c1[s][sn], a[s], b1[sn]);
                    mma_f16(c2[s][sn], a[s], b3[sn]);
                }
        }
        if (i + 1 < nk) {
            stsB((i + 1) & 1);
            if (i + 2 < nk) ldgB((i + 2) * BKH);
        }
        if (i + 2 < nk) loadA((i + 2) % 3, (i + 2) * BKH);
        CP_COMMIT();
    }
    CP_WAIT(0);

    // epilogue: hmid = silu(c1) * c2 * wr -> fp16
#pragma unroll
    for (int s = 0; s < 4; s++) {
#pragma unroll
        for (int half = 0; half < 2; half++) {
            int r = wm + s * 16 + half * 8 + lr;
            if (r < mrows) {
                float wr = g_pw[row0 + r];
                __half* hp = g_hmid + (size_t)(row0 + r) * FFN + n0;
#pragma unroll
                for (int sn = 0; sn < 2; sn++) {
                    int col = wn + sn * 8 + lc * 2;
                    float v1a = c1[s][sn][half * 2 + 0], v3a = c2[s][sn][half * 2 + 0];
                    float v1b = c1[s][sn][half * 2 + 1], v3b = c2[s][sn][half * 2 + 1];
                    float oa = (v1a / (1.f + expf(-v1a))) * v3a * wr;
                    float ob = (v1b / (1.f + expf(-v1b))) * v3b * wr;
                    *(uint32_t*)(hp + col) = pack_h2(oa, ob);
                }
            }
        }
    }

    // publish: hmid stores visible, then bump completion counter
    __threadfence();
    __syncthreads();
    if (tid == 0) atomicAdd(&g_done1[ti], 1u);
}

// ---------------- gemm2 tile: out[tok, n-chunk] += hmid @ w2^T ----------------
__device__ void gemm2_tile(int ti, int nx,
                           const float* __restrict__ w2,
                           float* __restrict__ out) {
    int e    = g_tile_e[ti];
    int mt   = g_tile_m[ti];
    int cnt  = g_cnt[e];
    int off  = g_off[e];
    int row0 = off + mt * MT;
    int mrows = cnt - mt * MT; if (mrows > MT) mrows = MT;
    int n0 = nx * 128;

    // wait for all gemm1 chunks of this m-tile
    if (threadIdx.x == 0) {
        while (atomicAdd(&g_done1[ti], 0u) < (unsigned)NCHUNK1) __nanosleep(200);
    }
    __syncthreads();
    __threadfence();

    extern __shared__ __half sm[];
    uint32_t smb = (uint32_t)__cvta_generic_to_shared(sm);

    int tid  = threadIdx.x;
    int wid  = tid >> 5, lane = tid & 31;
    int wm   = (wid & 3) * 64;
    int wn   = (wid >> 2) * 32;
    int lr   = lane >> 2, lc = lane & 3;

    uint32_t lm_off = (uint32_t)(((lane & 15) * PADH + (lane >> 4) * 8) * 2);

    const float* w2p = w2 + ((size_t)e * HID + n0) * FFN;

    const float* bsrc[2];
    uint32_t     bdst[2];
#pragma unroll
    for (int q = 0; q < 2; q++) {
        int idx = tid + q * 512;
        int row = idx >> 3, c8 = idx & 7;
        bsrc[q] = w2p + (size_t)row * FFN + c8 * 8;
        bdst[q] = smb + (uint32_t)((A_TOTH + row * PADH + c8 * 8) * 2);
    }

    float cc[4][4][4];
#pragma unroll
    for (int i = 0; i < 4; i++)
#pragma unroll
        for (int j = 0; j < 4; j++)
#pragma unroll
            for (int q = 0; q < 4; q++) cc[i][j][q] = 0.f;

    auto loadA = [&](int st, int k0) {
        uint32_t sb = smb + (uint32_t)(st * A_STH * 2);
#pragma unroll
        for (int j = 0; j < 4; j++) {
            int idx = j * 512 + tid;
            int row = idx >> 3, c8 = idx & 7;
            int p = (row < mrows) ? 16 : 0;
            cp_async16(sb + (uint32_t)((row * PADH + c8 * 8) * 2),
                       g_hmid + (size_t)(row0 + row) * FFN + k0 + c8 * 8, p);
        }
    };

    float4 rb[2][2];
    auto ldgB = [&](int k0) {
#pragma unroll
        for (int q = 0; q < 2; q++) {
            rb[q][0] = *(const float4*)(bsrc[q] + k0);
            rb[q][1] = *(const float4*)(bsrc[q] + k0 + 4);
        }
    };
    auto stsB = [&](int buf) {
#pragma unroll
        for (int q = 0; q < 2; q++) {
            STS128U(bdst[q] + (uint32_t)(buf * B_STH * 2),
                    pack_h2(rb[q][0].x, rb[q][0].y), pack_h2(rb[q][0].z, rb[q][0].w),
                    pack_h2(rb[q][1].x, rb[q][1].y), pack_h2(rb[q][1].z, rb[q][1].w));
        }
    };

    const int nk = FFN / BKH;   // 112

    ldgB(0);
    loadA(0, 0);   CP_COMMIT();
    loadA(1, BKH); CP_COMMIT();
    stsB(0);
    ldgB(BKH);

    for (int i = 0; i < nk; i++) {
        CP_WAIT(1);
        __syncthreads();
        uint32_t Sb = smb + (uint32_t)((i % 3) * A_STH * 2);
        uint32_t Bb = smb + (uint32_t)((A_TOTH + (i & 1) * B_STH) * 2);
#pragma unroll
        for (int ko = 0; ko < BKH; ko += 16) {
            unsigned a[4][4], b[4][2];
#pragma unroll
            for (int s = 0; s < 4; s++) {
                uint32_t ad = Sb + (uint32_t)(((wm + s * 16) * PADH + ko) * 2) + lm_off;
                LDSM_X4(a[s][0], a[s][1], a[s][2], a[s][3], ad);
            }
            {
                unsigned r0, r1, r2, r3;
                uint32_t bd0 = Bb + (uint32_t)((wn * PADH + ko) * 2) + lm_off;
                LDSM_X4(r0, r1, r2, r3, bd0);
                b[0][0] = r0; b[1][0] = r1; b[0][1] = r2; b[1][1] = r3;
                uint32_t bd1 = Bb + (uint32_t)(((wn + 16) * PADH + ko) * 2) + lm_off;
                LDSM_X4(r0, r1, r2, r3, bd1);
                b[2][0] = r0; b[3][0] = r1; b[2][1] = r2; b[3][1] = r3;
            }
#pragma unroll
            for (int s = 0; s < 4; s++)
#pragma unroll
                for (int sn = 0; sn < 4; sn++)
                    mma_f16(cc[s][sn], a[s], b[sn]);
        }
        if (i + 1 < nk) {
            stsB((i + 1) & 1);
            if (i + 2 < nk) ldgB((i + 2) * BKH);
        }
        if (i + 2 < nk) loadA((i + 2) % 3, (i + 2) * BKH);
        CP_COMMIT();
    }
    CP_WAIT(0);

    // epilogue: atomic scatter-add into out[token][h]
#pragma unroll
    for (int s = 0; s < 4; s++) {
#pragma unroll
        for (int half = 0; half < 2; half++) {
            int r = wm + s * 16 + half * 8 + lr;
            if (r < mrows) {
                int tok = g_ptok[row0 + r];
                float* op = out + (size_t)tok * HID + n0;
#pragma unroll
                for (int sn = 0; sn < 4; sn++) {
                    int col = wn + sn * 8 + lc * 2;
                    atomicAdd(&op[col + 0], cc[s][sn][half * 2 + 0]);
                    atomicAdd(&op[col + 1], cc[s][sn][half * 2 + 1]);
                }
            }
        }
    }
}

// ---------------- fused persistent GEMM kernel ----------------
__global__ __launch_bounds__(512, 1) void mm_kernel(const float* __restrict__ w1,
                                                    const float* __restrict__ w3,
                                                    const float* __restrict__ w2,
                                                    float* __restrict__ out) {
    __shared__ int s_item;
    const int n1   = g_n1;
    const int ntot = g_ntotal;

    while (true) {
        __syncthreads();   // all warps done with previous item's smem
        if (threadIdx.x == 0) s_item = (int)atomicAdd(&g_qhead, 1u);
        __syncthreads();
        int id = s_item;
        if (id >= ntot) break;
        if (id < n1) {
            gemm1_tile(id / NCHUNK1, id % NCHUNK1, w1, w3);
        } else {
            int id2 = id - n1;
            gemm2_tile(id2 / NCHUNK2, id2 % NCHUNK2, w2, out);
        }
    }
}

// ---------------- host launch ----------------
extern "C" void kernel_launch(void* const* d_in, const int* in_sizes, int n_in,
                              void* d_out, int out_size) {
    const float* x      = (const float*)d_in[0];
    const float* gate   = (const float*)d_in[1];
    const float* w1     = (const float*)d_in[2];
    const float* w3     = (const float*)d_in[3];
    const float* w2     = (const float*)d_in[4];
    const float* scales = (const float*)d_in[5];

    float* out = (float*)d_out;
    int write_logits = ((size_t)out_size >= OUT_ELEMS + (size_t)TOK * NE) ? 1 : 0;
    float* logits = out + OUT_ELEMS;

    cudaFuncSetAttribute(mm_kernel, cudaFuncAttributeMaxDynamicSharedMemorySize, SMEM_DYN);

    init_kernel<<<2048, 256>>>((float4*)out);
    router_kernel<<<TOK / 64, 256>>>(x, gate, logits, write_logits);
    scan_kernel<<<1, 128>>>();
    scatter_kernel<<<TOK / 256, 256>>>();
    gather_kernel<<<NPAIR, 128>>>(x, scales);

    mm_kernel<<<152, 512, SMEM_DYN>>>(w1, w3, w2, out);
}